// round 15
// baseline (speedup 1.0000x reference)
#include <cuda_runtime.h>
#include <cuda_bf16.h>
#include <cstdint>

#define B_    16
#define TRG_  512
#define SRC_  1024
#define ENC_  1024
#define TRGD_ 1024

// ---------------- packed bf16 hi/lo scratch (u32 = bf16x2 over k) -----------
__device__ uint32_t g_Hdh[(long)B_ * TRG_ * TRGD_ / 2];  // hidden   [t][d2]
__device__ uint32_t g_Hdl[(long)B_ * TRG_ * TRGD_ / 2];
__device__ uint32_t g_Eoh[(long)B_ * SRC_ * ENC_ / 2];   // enc_out  [s][e2]
__device__ uint32_t g_Eol[(long)B_ * SRC_ * ENC_ / 2];
__device__ uint32_t g_Wth[(long)ENC_ * TRGD_ / 2];       // W^T      [e][d2]
__device__ uint32_t g_Wtl[(long)ENC_ * TRGD_ / 2];
__device__ uint32_t g_Hph[(long)B_ * TRG_ * ENC_ / 2];   // hidden@W [t][e2]
__device__ uint32_t g_Hpl[(long)B_ * TRG_ * ENC_ / 2];
__device__ uint32_t g_Wgh[(long)B_ * TRG_ * SRC_ / 2];   // weights  [t][s2]
__device__ uint32_t g_Wgl[(long)B_ * TRG_ * SRC_ / 2];
__device__ uint32_t g_Evh[(long)B_ * SRC_ / 2 * TRGD_];  // enc_val  [s2][d] (NN pairs)
__device__ uint32_t g_Evl[(long)B_ * SRC_ / 2 * TRGD_];

// ---------------- helpers ----------------
__device__ __forceinline__ uint32_t s2u(const void* p) {
    uint32_t a;
    asm("{ .reg .u64 t; cvta.to.shared.u64 t, %1; cvt.u32.u64 %0, t; }"
        : "=r"(a) : "l"(p));
    return a;
}
__device__ __forceinline__ void bf16split2(float v0, float v1,
                                           uint32_t& ph, uint32_t& pl) {
    __nv_bfloat162 h = __floats2bfloat162_rn(v0, v1);
    ph = *reinterpret_cast<uint32_t*>(&h);
    float h0 = __uint_as_float(ph << 16);
    float h1 = __uint_as_float(ph & 0xFFFF0000u);
    __nv_bfloat162 l = __floats2bfloat162_rn(v0 - h0, v1 - h1);
    pl = *reinterpret_cast<uint32_t*>(&l);
}
__device__ __forceinline__ void cp16(uint32_t d, const void* s) {
    asm volatile("cp.async.cg.shared.global [%0], [%1], 16;" :: "r"(d), "l"(s));
}
#define CP_COMMIT() asm volatile("cp.async.commit_group;" ::: "memory")

#define MMA_BF16(acc, a0, a1, a2, a3, b0, b1) \
    asm volatile( \
        "mma.sync.aligned.m16n8k16.row.col.f32.bf16.bf16.f32 " \
        "{%0,%1,%2,%3}, {%4,%5,%6,%7}, {%8,%9}, {%0,%1,%2,%3};" \
        : "+f"((acc)[0]), "+f"((acc)[1]), "+f"((acc)[2]), "+f"((acc)[3]) \
        : "r"(a0), "r"(a1), "r"(a2), "r"(a3), "r"(b0), "r"(b1))

// ---------------------------------------------------------------------------
// bf16x3 GEMM: D[m,n] = sum_k A[m,k]*B[n,k]; inputs pre-split (separate hi/lo
// u32 arrays, bf16x2 over k). BM=BN=128, BK=16, FOUR-stage cp.async pipeline
// (3 chunks in flight, wait_group 2, one __syncthreads per chunk).
// 256 thr, warp tile 32x64, mma.m16n8k16, passes hh+hl+lh.
//   BNN=false: B K-major [n][k2=8] -> smem [n][12]  (12%32-bank CF)
//   BNN=true : B NN pairs [k2][n]  -> smem [k2=8][136]
// EPI: 0 = fp32 out, 1 = masked fp32 out, 2 = packed h/l u32 out.
// ---------------------------------------------------------------------------
template<int EPI, bool BNN>
__global__ __launch_bounds__(256, 2)
void gemm_bf16x3(const uint32_t* __restrict__ Ah, const uint32_t* __restrict__ Al,
                 const uint32_t* __restrict__ Bh, const uint32_t* __restrict__ Bl,
                 float* __restrict__ Cg, uint32_t* __restrict__ C2h,
                 uint32_t* __restrict__ C2l, const float* __restrict__ maskg,
                 int M, int N, int K, long sA, long sB, long sC)
{
    constexpr int STAGE = 6144;  // u32 per stage (24KB)
    constexpr int OAH = 0, OAL = 1536, OBH = 3072, OBL = 4608;

    extern __shared__ uint32_t smu[];

    const int tid  = threadIdx.x;
    const int wid  = tid >> 5, lane = tid & 31;
    const int wy   = wid >> 1, wx = wid & 1;
    const int bz   = blockIdx.z;
    const int bm   = blockIdx.y * 128, bn = blockIdx.x * 128;
    const int K2   = K >> 1;

    const uint32_t* Ah_ = Ah + (long)bz * sA + (long)bm * K2;
    const uint32_t* Al_ = Al + (long)bz * sA + (long)bm * K2;
    const uint32_t* Bh_ = BNN ? (Bh + (long)bz * sB)
                              : (Bh + (long)bz * sB + (long)bn * K2);
    const uint32_t* Bl_ = BNN ? (Bl + (long)bz * sB)
                              : (Bl + (long)bz * sB + (long)bn * K2);

    auto load_stage = [&](int s, int kc) {
        uint32_t* st = smu + s * STAGE;
        const int k2b = kc * 8;                 // 8 u32 (=16 k) per chunk
        {   // A tiles: 128 rows x 8 u32, one cp16 per thread per array
            int row = tid >> 1, ch = (tid & 1) * 4;
            cp16(s2u(st + OAH + row * 12 + ch), Ah_ + (long)row * K2 + k2b + ch);
            cp16(s2u(st + OAL + row * 12 + ch), Al_ + (long)row * K2 + k2b + ch);
        }
        if (BNN) {
            int r = tid >> 5, c = (tid & 31) * 4;
            cp16(s2u(st + OBH + r * 136 + c), Bh_ + (long)(k2b + r) * N + bn + c);
            cp16(s2u(st + OBL + r * 136 + c), Bl_ + (long)(k2b + r) * N + bn + c);
        } else {
            int row = tid >> 1, ch = (tid & 1) * 4;
            cp16(s2u(st + OBH + row * 12 + ch), Bh_ + (long)row * K2 + k2b + ch);
            cp16(s2u(st + OBL + row * 12 + ch), Bl_ + (long)row * K2 + k2b + ch);
        }
    };

    float acc[2][8][4];
#pragma unroll
    for (int i = 0; i < 2; i++)
#pragma unroll
        for (int j = 0; j < 8; j++)
#pragma unroll
            for (int v = 0; v < 4; v++) acc[i][j][v] = 0.0f;

    const int nch = K / 16;
    load_stage(0, 0); CP_COMMIT();
    load_stage(1, 1); CP_COMMIT();
    load_stage(2, 2); CP_COMMIT();

    const int aBase = (wy * 32 + (lane >> 2)) * 12 + (lane & 3);
    const int bBase = BNN ? ((lane & 3) * 136 + wx * 64 + (lane >> 2))
                          : ((wx * 64 + (lane >> 2)) * 12 + (lane & 3));

    for (int kc = 0; kc < nch; kc++) {
        asm volatile("cp.async.wait_group 2;" ::: "memory");
        __syncthreads();
        if (kc + 3 < nch) load_stage((kc + 3) & 3, kc + 3);
        CP_COMMIT();

        const uint32_t* st  = smu + (kc & 3) * STAGE;
        const uint32_t* sAh = st + OAH;
        const uint32_t* sAl = st + OAL;
        const uint32_t* sBh = st + OBH;
        const uint32_t* sBl = st + OBL;

        uint32_t ah[2][4], al[2][4];
#pragma unroll
        for (int i = 0; i < 2; i++) {
            const int o = aBase + i * 192;       // +16 rows * 12
            ah[i][0] = sAh[o];       ah[i][1] = sAh[o + 96];
            ah[i][2] = sAh[o + 4];   ah[i][3] = sAh[o + 100];
            al[i][0] = sAl[o];       al[i][1] = sAl[o + 96];
            al[i][2] = sAl[o + 4];   al[i][3] = sAl[o + 100];
        }
        auto loadB = [&](int j, uint32_t* bh, uint32_t* bl) {
            if (BNN) {
                const int o = bBase + j * 8;
                bh[0] = sBh[o]; bh[1] = sBh[o + 544];    // +4*136
                bl[0] = sBl[o]; bl[1] = sBl[o + 544];
            } else {
                const int o = bBase + j * 96;            // +8 rows * 12
                bh[0] = sBh[o]; bh[1] = sBh[o + 4];
                bl[0] = sBl[o]; bl[1] = sBl[o + 4];
            }
        };
        uint32_t bh0[2], bl0[2], bh1[2], bl1[2];
        loadB(0, bh0, bl0);
#pragma unroll
        for (int j = 0; j < 8; j++) {
            uint32_t* bh = (j & 1) ? bh1 : bh0;
            uint32_t* bl = (j & 1) ? bl1 : bl0;
            if (j < 7) loadB(j + 1, (j & 1) ? bh0 : bh1, (j & 1) ? bl0 : bl1);
            MMA_BF16(acc[0][j], ah[0][0], ah[0][1], ah[0][2], ah[0][3], bh[0], bh[1]);
            MMA_BF16(acc[1][j], ah[1][0], ah[1][1], ah[1][2], ah[1][3], bh[0], bh[1]);
            MMA_BF16(acc[0][j], ah[0][0], ah[0][1], ah[0][2], ah[0][3], bl[0], bl[1]);
            MMA_BF16(acc[1][j], ah[1][0], ah[1][1], ah[1][2], ah[1][3], bl[0], bl[1]);
            MMA_BF16(acc[0][j], al[0][0], al[0][1], al[0][2], al[0][3], bh[0], bh[1]);
            MMA_BF16(acc[1][j], al[1][0], al[1][1], al[1][2], al[1][3], bh[0], bh[1]);
        }
    }

    // epilogue
    const int N2 = N >> 1;
#pragma unroll
    for (int i = 0; i < 2; i++) {
        const int row = bm + wy * 32 + i * 16 + (lane >> 2);
#pragma unroll
        for (int j = 0; j < 8; j++) {
            const int col = bn + wx * 64 + j * 8 + (lane & 3) * 2;
            float v0 = acc[i][j][0], v1 = acc[i][j][1];
            float v2 = acc[i][j][2], v3 = acc[i][j][3];
            if (EPI == 2) {
                uint32_t ph, pl;
                bf16split2(v0, v1, ph, pl);
                C2h[(long)row * N2 + (col >> 1)] = ph;
                C2l[(long)row * N2 + (col >> 1)] = pl;
                bf16split2(v2, v3, ph, pl);
                C2h[(long)(row + 8) * N2 + (col >> 1)] = ph;
                C2l[(long)(row + 8) * N2 + (col >> 1)] = pl;
            } else {
                float* C = Cg + (long)bz * sC;
                if (EPI == 1) {
                    float m0 = maskg[(long)bz * N + col];
                    float m1 = maskg[(long)bz * N + col + 1];
                    v0 *= m0; v1 *= m1; v2 *= m0; v3 *= m1;
                }
                float2 p01; p01.x = v0; p01.y = v1;
                float2 p23; p23.x = v2; p23.y = v3;
                *reinterpret_cast<float2*>(&C[(long)row * N + col]) = p01;
                *reinterpret_cast<float2*>(&C[(long)(row + 8) * N + col]) = p23;
            }
        }
    }
}

// ---------------- split kernels ----------------
__global__ __launch_bounds__(256)
void split_pack_k(const float2* __restrict__ in, uint32_t* __restrict__ h,
                  uint32_t* __restrict__ l, long n2)
{
    long i = (long)blockIdx.x * blockDim.x + threadIdx.x;
    if (i < n2) {
        float2 v = in[i];
        uint32_t ph, pl;
        bf16split2(v.x, v.y, ph, pl);
        h[i] = ph; l[i] = pl;
    }
}

// W[d][e] -> packed transpose Wt[e][d2] (pairs over d)
__global__ __launch_bounds__(256)
void transpose_split_pack_k(const float* __restrict__ W,
                            uint32_t* __restrict__ th, uint32_t* __restrict__ tl)
{
    __shared__ float t[32][33];
    const int d0 = blockIdx.y * 32, e0 = blockIdx.x * 32;
    const int x = threadIdx.x & 31, y = threadIdx.x >> 5;
#pragma unroll
    for (int i = 0; i < 4; i++)
        t[y + 8 * i][x] = W[(long)(d0 + y + 8 * i) * ENC_ + e0 + x];
    __syncthreads();
#pragma unroll
    for (int it = 0; it < 2; it++) {
        int idx = threadIdx.x + 256 * it;
        int e = idx >> 4, d2 = idx & 15;
        uint32_t ph, pl;
        bf16split2(t[2 * d2][e], t[2 * d2 + 1][e], ph, pl);
        th[(long)(e0 + e) * (TRGD_ / 2) + (d0 >> 1) + d2] = ph;
        tl[(long)(e0 + e) * (TRGD_ / 2) + (d0 >> 1) + d2] = pl;
    }
}

// enc_val row pairs: Ev[s][d] -> packed [s2][d] (pairs over s)
__global__ __launch_bounds__(256)
void pack_rows2_k(const float* __restrict__ in, uint32_t* __restrict__ h,
                  uint32_t* __restrict__ l)
{
    const int r = blockIdx.y;
    const int c = blockIdx.x * 256 + threadIdx.x;
    float v0 = in[(long)(2 * r) * TRGD_ + c];
    float v1 = in[(long)(2 * r + 1) * TRGD_ + c];
    uint32_t ph, pl;
    bf16split2(v0, v1, ph, pl);
    h[(long)r * TRGD_ + c] = ph;
    l[(long)r * TRGD_ + c] = pl;
}

// ---------------- masked softmax; exact fp32 + packed h/l outputs ----------
__global__ __launch_bounds__(256)
void masked_softmax_k(const float* __restrict__ energ, const float* __restrict__ mask,
                      float* __restrict__ wout, uint32_t* __restrict__ wh,
                      uint32_t* __restrict__ wl)
{
    const int row = blockIdx.x;
    const int b = row >> 9;
    const float4* xr = reinterpret_cast<const float4*>(energ + (long)row * SRC_);
    const float4* mr = reinterpret_cast<const float4*>(mask + (long)b * SRC_);
    float4* wr = reinterpret_cast<float4*>(wout + (long)row * SRC_);
    const int t = threadIdx.x;

    float4 xv = xr[t];
    float4 mv = mr[t];
    xv.x *= mv.x; xv.y *= mv.y; xv.z *= mv.z; xv.w *= mv.w;

    float lmax = fmaxf(fmaxf(xv.x, xv.y), fmaxf(xv.z, xv.w));
#pragma unroll
    for (int o = 16; o; o >>= 1)
        lmax = fmaxf(lmax, __shfl_xor_sync(0xffffffffu, lmax, o));

    __shared__ float redm[8];
    __shared__ float reds[8];
    if ((t & 31) == 0) redm[t >> 5] = lmax;
    __syncthreads();
    float bmax = fmaxf(fmaxf(fmaxf(redm[0], redm[1]), fmaxf(redm[2], redm[3])),
                       fmaxf(fmaxf(redm[4], redm[5]), fmaxf(redm[6], redm[7])));

    float4 ev;
    ev.x = expf(xv.x - bmax) * mv.x;
    ev.y = expf(xv.y - bmax) * mv.y;
    ev.z = expf(xv.z - bmax) * mv.z;
    ev.w = expf(xv.w - bmax) * mv.w;

    float lsum = ev.x + ev.y + ev.z + ev.w;
#pragma unroll
    for (int o = 16; o; o >>= 1)
        lsum += __shfl_xor_sync(0xffffffffu, lsum, o);
    if ((t & 31) == 0) reds[t >> 5] = lsum;
    __syncthreads();
    float bsum = reds[0] + reds[1] + reds[2] + reds[3] +
                 reds[4] + reds[5] + reds[6] + reds[7];

    float inv = 1.0f / (bsum + 1e-6f);
    ev.x *= inv; ev.y *= inv; ev.z *= inv; ev.w *= inv;
    wr[t] = ev;

    uint32_t ph, pl;
    const long p = (long)row * (SRC_ / 2) + 2 * t;
    bf16split2(ev.x, ev.y, ph, pl);
    wh[p] = ph; wl[p] = pl;
    bf16split2(ev.z, ev.w, ph, pl);
    wh[p + 1] = ph; wl[p + 1] = pl;
}

// ---------------- launch ----------------
extern "C" void kernel_launch(void* const* d_in, const int* in_sizes, int n_in,
                              void* d_out, int out_size)
{
    const float* hidden  = (const float*)d_in[0];   // (B, TRG, TRGD)
    const float* enc_out = (const float*)d_in[1];   // (B, SRC, ENC)
    const float* enc_val = (const float*)d_in[2];   // (B, SRC, TRGD)
    const float* mask    = (const float*)d_in[3];   // (B, SRC)
    const float* W       = (const float*)d_in[4];   // (TRGD, ENC)

    float* out      = (float*)d_out;
    float* context  = out;                           // (B, TRG, TRGD)
    float* weights  = out + (long)B_ * TRG_ * SRC_;  // (B, TRG, SRC)
    float* energies = out + 2L * B_ * TRG_ * SRC_;   // (B, TRG, SRC)

    uint32_t *Hdh, *Hdl, *Eoh, *Eol, *Wth, *Wtl, *Hph, *Hpl, *Wgh, *Wgl, *Evh, *Evl;
    cudaGetSymbolAddress((void**)&Hdh, g_Hdh);
    cudaGetSymbolAddress((void**)&Hdl, g_Hdl);
    cudaGetSymbolAddress((void**)&Eoh, g_Eoh);
    cudaGetSymbolAddress((void**)&Eol, g_Eol);
    cudaGetSymbolAddress((void**)&Wth, g_Wth);
    cudaGetSymbolAddress((void**)&Wtl, g_Wtl);
    cudaGetSymbolAddress((void**)&Hph, g_Hph);
    cudaGetSymbolAddress((void**)&Hpl, g_Hpl);
    cudaGetSymbolAddress((void**)&Wgh, g_Wgh);
    cudaGetSymbolAddress((void**)&Wgl, g_Wgl);
    cudaGetSymbolAddress((void**)&Evh, g_Evh);
    cudaGetSymbolAddress((void**)&Evl, g_Evl);

    const size_t dyn = 4UL * 6144 * 4;   // 98,304 B
    cudaFuncSetAttribute(gemm_bf16x3<2, false>,
                         cudaFuncAttributeMaxDynamicSharedMemorySize, dyn);
    cudaFuncSetAttribute(gemm_bf16x3<1, false>,
                         cudaFuncAttributeMaxDynamicSharedMemorySize, dyn);
    cudaFuncSetAttribute(gemm_bf16x3<0, true>,
                         cudaFuncAttributeMaxDynamicSharedMemorySize, dyn);

    // splits
    {
        long n2 = (long)B_ * TRG_ * TRGD_ / 2;
        split_pack_k<<<(unsigned)((n2 + 255) / 256), 256>>>(
            (const float2*)hidden, Hdh, Hdl, n2);
    }
    {
        long n2 = (long)B_ * SRC_ * ENC_ / 2;
        split_pack_k<<<(unsigned)((n2 + 255) / 256), 256>>>(
            (const float2*)enc_out, Eoh, Eol, n2);
    }
    transpose_split_pack_k<<<dim3(ENC_ / 32, TRGD_ / 32), 256>>>(W, Wth, Wtl);
    pack_rows2_k<<<dim3(TRGD_ / 256, B_ * SRC_ / 2), 256>>>(enc_val, Evh, Evl);

    // 1) Hp = hidden @ W  -> packed bf16 h/l   (A=hidden, B=Wt, K-major)
    {
        dim3 grid(ENC_ / 128, (B_ * TRG_) / 128, 1);
        gemm_bf16x3<2, false><<<grid, 256, dyn>>>(
            Hdh, Hdl, Wth, Wtl, nullptr, Hph, Hpl, nullptr,
            B_ * TRG_, ENC_, TRGD_, 0, 0, 0);
    }
    // 2) energies[b] = (Hp[b] @ enc_out[b]^T) * mask[b]
    {
        dim3 grid(SRC_ / 128, TRG_ / 128, B_);
        gemm_bf16x3<1, false><<<grid, 256, dyn>>>(
            Hph, Hpl, Eoh, Eol, energies, nullptr, nullptr, mask,
            TRG_, SRC_, ENC_,
            (long)TRG_ * ENC_ / 2, (long)SRC_ * ENC_ / 2, (long)TRG_ * SRC_);
    }
    // 3) masked softmax -> weights (fp32) + packed h/l
    masked_softmax_k<<<B_ * TRG_, 256>>>(energies, mask, weights, Wgh, Wgl);

    // 4) context[b] = weights[b] @ enc_val[b]   (B NN pairs layout)
    {
        dim3 grid(TRGD_ / 128, TRG_ / 128, B_);
        gemm_bf16x3<0, true><<<grid, 256, dyn>>>(
            Wgh, Wgl, Evh, Evl, context, nullptr, nullptr, nullptr,
            TRG_, TRGD_, SRC_,
            (long)TRG_ * SRC_ / 2, (long)SRC_ / 2 * TRGD_, (long)TRG_ * TRGD_);
    }
}

// round 16
// speedup vs baseline: 1.1407x; 1.1407x over previous
#include <cuda_runtime.h>
#include <cuda_bf16.h>
#include <cstdint>

#define B_    16
#define TRG_  512
#define SRC_  1024
#define ENC_  1024
#define TRGD_ 1024

// ---------------- packed bf16 hi/lo scratch (u32 = bf16x2 over k) -----------
__device__ uint32_t g_Hdh[(long)B_ * TRG_ * TRGD_ / 2];  // hidden   [t][d2]
__device__ uint32_t g_Hdl[(long)B_ * TRG_ * TRGD_ / 2];
__device__ uint32_t g_Eoh[(long)B_ * SRC_ * ENC_ / 2];   // enc_out  [s][e2]
__device__ uint32_t g_Eol[(long)B_ * SRC_ * ENC_ / 2];
__device__ uint32_t g_Wth[(long)ENC_ * TRGD_ / 2];       // W^T      [e][d2]
__device__ uint32_t g_Wtl[(long)ENC_ * TRGD_ / 2];
__device__ uint32_t g_Hph[(long)B_ * TRG_ * ENC_ / 2];   // hidden@W [t][e2]
__device__ uint32_t g_Hpl[(long)B_ * TRG_ * ENC_ / 2];
__device__ uint32_t g_Wgh[(long)B_ * TRG_ * SRC_ / 2];   // weights  [t][s2]
__device__ uint32_t g_Wgl[(long)B_ * TRG_ * SRC_ / 2];
__device__ uint32_t g_Evh[(long)B_ * SRC_ / 2 * TRGD_];  // enc_val  [s2][d] (NN pairs)
__device__ uint32_t g_Evl[(long)B_ * SRC_ / 2 * TRGD_];

// ---------------- helpers ----------------
__device__ __forceinline__ uint32_t s2u(const void* p) {
    uint32_t a;
    asm("{ .reg .u64 t; cvta.to.shared.u64 t, %1; cvt.u32.u64 %0, t; }"
        : "=r"(a) : "l"(p));
    return a;
}
__device__ __forceinline__ void bf16split2(float v0, float v1,
                                           uint32_t& ph, uint32_t& pl) {
    __nv_bfloat162 h = __floats2bfloat162_rn(v0, v1);
    ph = *reinterpret_cast<uint32_t*>(&h);
    float h0 = __uint_as_float(ph << 16);
    float h1 = __uint_as_float(ph & 0xFFFF0000u);
    __nv_bfloat162 l = __floats2bfloat162_rn(v0 - h0, v1 - h1);
    pl = *reinterpret_cast<uint32_t*>(&l);
}
__device__ __forceinline__ void cp16(uint32_t d, const void* s) {
    asm volatile("cp.async.cg.shared.global [%0], [%1], 16;" :: "r"(d), "l"(s));
}
#define CP_COMMIT() asm volatile("cp.async.commit_group;" ::: "memory")

#define MMA_BF16(acc, a0, a1, a2, a3, b0, b1) \
    asm volatile( \
        "mma.sync.aligned.m16n8k16.row.col.f32.bf16.bf16.f32 " \
        "{%0,%1,%2,%3}, {%4,%5,%6,%7}, {%8,%9}, {%0,%1,%2,%3};" \
        : "+f"((acc)[0]), "+f"((acc)[1]), "+f"((acc)[2]), "+f"((acc)[3]) \
        : "r"(a0), "r"(a1), "r"(a2), "r"(a3), "r"(b0), "r"(b1))

// ---------------------------------------------------------------------------
// bf16x3 GEMM (round-9 baseline): D[m,n] = sum_k A[m,k]*B[n,k]; inputs
// pre-split into separate hi/lo u32 arrays (bf16x2 over k). BM=BN=128, BK=32,
// 2-stage cp.async, 256 thr, warp tile 32x64, passes hh+hl+lh.
//   BNN=false: B K-major packed [n][k2] -> smem [n][20] u32 (pad)
//   BNN=true : B NN pairs packed [k2][n] -> smem [k2][136] u32
// EPI: 0 = fp32 out, 1 = masked fp32 out, 2 = packed bf16 h/l out.
// ---------------------------------------------------------------------------
template<int EPI, bool BNN>
__global__ __launch_bounds__(256, 2)
void gemm_bf16x3(const uint32_t* __restrict__ Ah, const uint32_t* __restrict__ Al,
                 const uint32_t* __restrict__ Bh, const uint32_t* __restrict__ Bl,
                 float* __restrict__ Cg, uint32_t* __restrict__ C2h,
                 uint32_t* __restrict__ C2l, const float* __restrict__ maskg,
                 int M, int N, int K, long sA, long sB, long sC)
{
    constexpr int STAGE = 10240;          // u32 per stage (40KB)
    constexpr int OAH = 0, OAL = 2560, OBH = 5120, OBL = 7680;

    extern __shared__ uint32_t smu[];

    const int tid  = threadIdx.x;
    const int wid  = tid >> 5, lane = tid & 31;
    const int wy   = wid >> 1, wx = wid & 1;
    const int bz   = blockIdx.z;
    const int bm   = blockIdx.y * 128, bn = blockIdx.x * 128;
    const int K2   = K >> 1;

    const uint32_t* Ah_ = Ah + (long)bz * sA + (long)bm * K2;
    const uint32_t* Al_ = Al + (long)bz * sA + (long)bm * K2;
    const uint32_t* Bh_ = BNN ? (Bh + (long)bz * sB)
                              : (Bh + (long)bz * sB + (long)bn * K2);
    const uint32_t* Bl_ = BNN ? (Bl + (long)bz * sB)
                              : (Bl + (long)bz * sB + (long)bn * K2);

    auto load_stage = [&](int s, int kc) {
        uint32_t* st = smu + s * STAGE;
        const int k2b = kc * 16;   // 16 u32 (=32 k) per chunk
#pragma unroll
        for (int i = 0; i < 2; i++) {
            int id = tid + 256 * i;
            int row = id >> 2, ch = (id & 3) * 4;
            cp16(s2u(st + OAH + row * 20 + ch), Ah_ + (long)row * K2 + k2b + ch);
            cp16(s2u(st + OAL + row * 20 + ch), Al_ + (long)row * K2 + k2b + ch);
        }
        if (BNN) {
#pragma unroll
            for (int i = 0; i < 2; i++) {
                int id = tid + 256 * i;
                int r = id >> 5, c = (id & 31) * 4;
                cp16(s2u(st + OBH + r * 136 + c), Bh_ + (long)(k2b + r) * N + bn + c);
                cp16(s2u(st + OBL + r * 136 + c), Bl_ + (long)(k2b + r) * N + bn + c);
            }
        } else {
#pragma unroll
            for (int i = 0; i < 2; i++) {
                int id = tid + 256 * i;
                int row = id >> 2, ch = (id & 3) * 4;
                cp16(s2u(st + OBH + row * 20 + ch), Bh_ + (long)row * K2 + k2b + ch);
                cp16(s2u(st + OBL + row * 20 + ch), Bl_ + (long)row * K2 + k2b + ch);
            }
        }
    };

    float acc[2][8][4];
#pragma unroll
    for (int i = 0; i < 2; i++)
#pragma unroll
        for (int j = 0; j < 8; j++)
#pragma unroll
            for (int v = 0; v < 4; v++) acc[i][j][v] = 0.0f;

    const int nch = K / 32;
    load_stage(0, 0); CP_COMMIT();

    const int aBase = (wy * 32 + (lane >> 2)) * 20 + (lane & 3);
    const int bBase = BNN ? ((lane & 3) * 136 + wx * 64 + (lane >> 2))
                          : ((wx * 64 + (lane >> 2)) * 20 + (lane & 3));

    for (int kc = 0; kc < nch; kc++) {
        if (kc + 1 < nch) {
            load_stage((kc + 1) & 1, kc + 1);
            CP_COMMIT();
            asm volatile("cp.async.wait_group 1;" ::: "memory");
        } else {
            asm volatile("cp.async.wait_group 0;" ::: "memory");
        }
        __syncthreads();

        const uint32_t* st  = smu + (kc & 1) * STAGE;
        const uint32_t* sAh = st + OAH;
        const uint32_t* sAl = st + OAL;
        const uint32_t* sBh = st + OBH;
        const uint32_t* sBl = st + OBL;

#pragma unroll
        for (int ks = 0; ks < 2; ks++) {
            const int ak = aBase + ks * 8;
            uint32_t ah[2][4], al[2][4];
#pragma unroll
            for (int i = 0; i < 2; i++) {
                const int o = ak + i * 16 * 20;
                ah[i][0] = sAh[o];           ah[i][1] = sAh[o + 8 * 20];
                ah[i][2] = sAh[o + 4];       ah[i][3] = sAh[o + 8 * 20 + 4];
                al[i][0] = sAl[o];           al[i][1] = sAl[o + 8 * 20];
                al[i][2] = sAl[o + 4];       al[i][3] = sAl[o + 8 * 20 + 4];
            }
            const int bk = bBase + (BNN ? ks * 8 * 136 : ks * 8);
            const int bd = BNN ? 4 * 136 : 4;
            auto loadB = [&](int j, uint32_t* bh, uint32_t* bl) {
                const int o = bk + (BNN ? j * 8 : j * 8 * 20);
                bh[0] = sBh[o]; bh[1] = sBh[o + bd];
                bl[0] = sBl[o]; bl[1] = sBl[o + bd];
            };
            uint32_t bh0[2], bl0[2], bh1[2], bl1[2];
            loadB(0, bh0, bl0);
#pragma unroll
            for (int j = 0; j < 8; j++) {
                uint32_t* bh = (j & 1) ? bh1 : bh0;
                uint32_t* bl = (j & 1) ? bl1 : bl0;
                if (j < 7) loadB(j + 1, (j & 1) ? bh0 : bh1, (j & 1) ? bl0 : bl1);
                MMA_BF16(acc[0][j], ah[0][0], ah[0][1], ah[0][2], ah[0][3], bh[0], bh[1]);
                MMA_BF16(acc[1][j], ah[1][0], ah[1][1], ah[1][2], ah[1][3], bh[0], bh[1]);
                MMA_BF16(acc[0][j], ah[0][0], ah[0][1], ah[0][2], ah[0][3], bl[0], bl[1]);
                MMA_BF16(acc[1][j], ah[1][0], ah[1][1], ah[1][2], ah[1][3], bl[0], bl[1]);
                MMA_BF16(acc[0][j], al[0][0], al[0][1], al[0][2], al[0][3], bh[0], bh[1]);
                MMA_BF16(acc[1][j], al[1][0], al[1][1], al[1][2], al[1][3], bh[0], bh[1]);
            }
        }
        __syncthreads();
    }

    // epilogue
    const int N2 = N >> 1;
#pragma unroll
    for (int i = 0; i < 2; i++) {
        const int row = bm + wy * 32 + i * 16 + (lane >> 2);
#pragma unroll
        for (int j = 0; j < 8; j++) {
            const int col = bn + wx * 64 + j * 8 + (lane & 3) * 2;
            float v0 = acc[i][j][0], v1 = acc[i][j][1];
            float v2 = acc[i][j][2], v3 = acc[i][j][3];
            if (EPI == 2) {
                uint32_t ph, pl;
                bf16split2(v0, v1, ph, pl);
                C2h[(long)row * N2 + (col >> 1)] = ph;
                C2l[(long)row * N2 + (col >> 1)] = pl;
                bf16split2(v2, v3, ph, pl);
                C2h[(long)(row + 8) * N2 + (col >> 1)] = ph;
                C2l[(long)(row + 8) * N2 + (col >> 1)] = pl;
            } else {
                float* C = Cg + (long)bz * sC;
                if (EPI == 1) {
                    float m0 = maskg[(long)bz * N + col];
                    float m1 = maskg[(long)bz * N + col + 1];
                    v0 *= m0; v1 *= m1; v2 *= m0; v3 *= m1;
                }
                float2 p01; p01.x = v0; p01.y = v1;
                float2 p23; p23.x = v2; p23.y = v3;
                *reinterpret_cast<float2*>(&C[(long)row * N + col]) = p01;
                *reinterpret_cast<float2*>(&C[(long)(row + 8) * N + col]) = p23;
            }
        }
    }
}

// ---------------- split kernels (vectorized: 4 outputs/thread) --------------
// contiguous k-pairs (hidden, enc_out): 8 floats in -> uint4 h + uint4 l
__global__ __launch_bounds__(256)
void split_pack_k(const float4* __restrict__ in, uint4* __restrict__ h,
                  uint4* __restrict__ l, long nv)
{
    long i = (long)blockIdx.x * blockDim.x + threadIdx.x;
    if (i < nv) {
        float4 a = in[2 * i];
        float4 b = in[2 * i + 1];
        uint4 ho, lo;
        bf16split2(a.x, a.y, ho.x, lo.x);
        bf16split2(a.z, a.w, ho.y, lo.y);
        bf16split2(b.x, b.y, ho.z, lo.z);
        bf16split2(b.z, b.w, ho.w, lo.w);
        h[i] = ho; l[i] = lo;
    }
}

// W[d][e] -> packed transpose Wt[e][d2] (pairs over d) -- small, unchanged
__global__ __launch_bounds__(256)
void transpose_split_pack_k(const float* __restrict__ W,
                            uint32_t* __restrict__ th, uint32_t* __restrict__ tl)
{
    __shared__ float t[32][33];
    const int d0 = blockIdx.y * 32, e0 = blockIdx.x * 32;
    const int x = threadIdx.x & 31, y = threadIdx.x >> 5;
#pragma unroll
    for (int i = 0; i < 4; i++)
        t[y + 8 * i][x] = W[(long)(d0 + y + 8 * i) * ENC_ + e0 + x];
    __syncthreads();
#pragma unroll
    for (int it = 0; it < 2; it++) {
        int idx = threadIdx.x + 256 * it;
        int e = idx >> 4, d2 = idx & 15;
        uint32_t ph, pl;
        bf16split2(t[2 * d2][e], t[2 * d2 + 1][e], ph, pl);
        th[(long)(e0 + e) * (TRGD_ / 2) + (d0 >> 1) + d2] = ph;
        tl[(long)(e0 + e) * (TRGD_ / 2) + (d0 >> 1) + d2] = pl;
    }
}

// enc_val row pairs: Ev[s][d] -> packed [s2][d]; 4 columns per thread
__global__ __launch_bounds__(256)
void pack_rows2_k(const float* __restrict__ in, uint4* __restrict__ h,
                  uint4* __restrict__ l)
{
    const int r = blockIdx.x;                            // global s2 row
    const int c = threadIdx.x * 4;                       // d (TRGD_/4 = 256 thr)
    float4 a = *reinterpret_cast<const float4*>(in + (long)(2 * r) * TRGD_ + c);
    float4 b = *reinterpret_cast<const float4*>(in + (long)(2 * r + 1) * TRGD_ + c);
    uint4 ho, lo;
    bf16split2(a.x, b.x, ho.x, lo.x);
    bf16split2(a.y, b.y, ho.y, lo.y);
    bf16split2(a.z, b.z, ho.z, lo.z);
    bf16split2(a.w, b.w, ho.w, lo.w);
    const long p = ((long)r * TRGD_ + c) >> 2;
    h[p] = ho; l[p] = lo;
}

// ---------------- masked softmax; exact fp32 + packed h/l outputs ----------
__global__ __launch_bounds__(256)
void masked_softmax_k(const float* __restrict__ energ, const float* __restrict__ mask,
                      float* __restrict__ wout, uint32_t* __restrict__ wh,
                      uint32_t* __restrict__ wl)
{
    const int row = blockIdx.x;
    const int b = row >> 9;
    const float4* xr = reinterpret_cast<const float4*>(energ + (long)row * SRC_);
    const float4* mr = reinterpret_cast<const float4*>(mask + (long)b * SRC_);
    float4* wr = reinterpret_cast<float4*>(wout + (long)row * SRC_);
    const int t = threadIdx.x;

    float4 xv = xr[t];
    float4 mv = mr[t];
    xv.x *= mv.x; xv.y *= mv.y; xv.z *= mv.z; xv.w *= mv.w;

    float lmax = fmaxf(fmaxf(xv.x, xv.y), fmaxf(xv.z, xv.w));
#pragma unroll
    for (int o = 16; o; o >>= 1)
        lmax = fmaxf(lmax, __shfl_xor_sync(0xffffffffu, lmax, o));

    __shared__ float redm[8];
    __shared__ float reds[8];
    if ((t & 31) == 0) redm[t >> 5] = lmax;
    __syncthreads();
    float bmax = fmaxf(fmaxf(fmaxf(redm[0], redm[1]), fmaxf(redm[2], redm[3])),
                       fmaxf(fmaxf(redm[4], redm[5]), fmaxf(redm[6], redm[7])));

    float4 ev;
    ev.x = expf(xv.x - bmax) * mv.x;
    ev.y = expf(xv.y - bmax) * mv.y;
    ev.z = expf(xv.z - bmax) * mv.z;
    ev.w = expf(xv.w - bmax) * mv.w;

    float lsum = ev.x + ev.y + ev.z + ev.w;
#pragma unroll
    for (int o = 16; o; o >>= 1)
        lsum += __shfl_xor_sync(0xffffffffu, lsum, o);
    if ((t & 31) == 0) reds[t >> 5] = lsum;
    __syncthreads();
    float bsum = reds[0] + reds[1] + reds[2] + reds[3] +
                 reds[4] + reds[5] + reds[6] + reds[7];

    float inv = 1.0f / (bsum + 1e-6f);
    ev.x *= inv; ev.y *= inv; ev.z *= inv; ev.w *= inv;
    wr[t] = ev;

    uint32_t ph, pl;
    const long p = (long)row * (SRC_ / 2) + 2 * t;
    bf16split2(ev.x, ev.y, ph, pl);
    wh[p] = ph; wl[p] = pl;
    bf16split2(ev.z, ev.w, ph, pl);
    wh[p + 1] = ph; wl[p + 1] = pl;
}

// ---------------- launch ----------------
extern "C" void kernel_launch(void* const* d_in, const int* in_sizes, int n_in,
                              void* d_out, int out_size)
{
    const float* hidden  = (const float*)d_in[0];   // (B, TRG, TRGD)
    const float* enc_out = (const float*)d_in[1];   // (B, SRC, ENC)
    const float* enc_val = (const float*)d_in[2];   // (B, SRC, TRGD)
    const float* mask    = (const float*)d_in[3];   // (B, SRC)
    const float* W       = (const float*)d_in[4];   // (TRGD, ENC)

    float* out      = (float*)d_out;
    float* context  = out;                           // (B, TRG, TRGD)
    float* weights  = out + (long)B_ * TRG_ * SRC_;  // (B, TRG, SRC)
    float* energies = out + 2L * B_ * TRG_ * SRC_;   // (B, TRG, SRC)

    uint32_t *Hdh, *Hdl, *Eoh, *Eol, *Wth, *Wtl, *Hph, *Hpl, *Wgh, *Wgl, *Evh, *Evl;
    cudaGetSymbolAddress((void**)&Hdh, g_Hdh);
    cudaGetSymbolAddress((void**)&Hdl, g_Hdl);
    cudaGetSymbolAddress((void**)&Eoh, g_Eoh);
    cudaGetSymbolAddress((void**)&Eol, g_Eol);
    cudaGetSymbolAddress((void**)&Wth, g_Wth);
    cudaGetSymbolAddress((void**)&Wtl, g_Wtl);
    cudaGetSymbolAddress((void**)&Hph, g_Hph);
    cudaGetSymbolAddress((void**)&Hpl, g_Hpl);
    cudaGetSymbolAddress((void**)&Wgh, g_Wgh);
    cudaGetSymbolAddress((void**)&Wgl, g_Wgl);
    cudaGetSymbolAddress((void**)&Evh, g_Evh);
    cudaGetSymbolAddress((void**)&Evl, g_Evl);

    const size_t dyn = 2UL * 10240 * 4;   // 81,920 B
    cudaFuncSetAttribute(gemm_bf16x3<2, false>,
                         cudaFuncAttributeMaxDynamicSharedMemorySize, dyn);
    cudaFuncSetAttribute(gemm_bf16x3<1, false>,
                         cudaFuncAttributeMaxDynamicSharedMemorySize, dyn);
    cudaFuncSetAttribute(gemm_bf16x3<0, true>,
                         cudaFuncAttributeMaxDynamicSharedMemorySize, dyn);

    // splits (vectorized)
    {
        long nv = (long)B_ * TRG_ * TRGD_ / 8;   // 4 pairs per thread
        split_pack_k<<<(unsigned)((nv + 255) / 256), 256>>>(
            (const float4*)hidden, (uint4*)Hdh, (uint4*)Hdl, nv);
    }
    {
        long nv = (long)B_ * SRC_ * ENC_ / 8;
        split_pack_k<<<(unsigned)((nv + 255) / 256), 256>>>(
            (const float4*)enc_out, (uint4*)Eoh, (uint4*)Eol, nv);
    }
    transpose_split_pack_k<<<dim3(ENC_ / 32, TRGD_ / 32), 256>>>(W, Wth, Wtl);
    pack_rows2_k<<<B_ * SRC_ / 2, TRGD_ / 4>>>(enc_val, (uint4*)Evh, (uint4*)Evl);

    // 1) Hp = hidden @ W  -> packed bf16 h/l   (A=hidden, B=Wt, K-major)
    {
        dim3 grid(ENC_ / 128, (B_ * TRG_) / 128, 1);
        gemm_bf16x3<2, false><<<grid, 256, dyn>>>(
            Hdh, Hdl, Wth, Wtl, nullptr, Hph, Hpl, nullptr,
            B_ * TRG_, ENC_, TRGD_, 0, 0, 0);
    }
    // 2) energies[b] = (Hp[b] @ enc_out[b]^T) * mask[b]
    {
        dim3 grid(SRC_ / 128, TRG_ / 128, B_);
        gemm_bf16x3<1, false><<<grid, 256, dyn>>>(
            Hph, Hpl, Eoh, Eol, energies, nullptr, nullptr, mask,
            TRG_, SRC_, ENC_,
            (long)TRG_ * ENC_ / 2, (long)SRC_ * ENC_ / 2, (long)TRG_ * SRC_);
    }
    // 3) masked softmax -> weights (fp32) + packed h/l
    masked_softmax_k<<<B_ * TRG_, 256>>>(energies, mask, weights, Wgh, Wgl);

    // 4) context[b] = weights[b] @ enc_val[b]   (B NN pairs layout)
    {
        dim3 grid(TRGD_ / 128, TRG_ / 128, B_);
        gemm_bf16x3<0, true><<<grid, 256, dyn>>>(
            Wgh, Wgl, Evh, Evl, context, nullptr, nullptr, nullptr,
            TRG_, TRGD_, SRC_,
            (long)TRG_ * SRC_ / 2, (long)SRC_ / 2 * TRGD_, (long)TRG_ * TRGD_);
    }
}

// round 17
// speedup vs baseline: 1.2013x; 1.0531x over previous
#include <cuda_runtime.h>
#include <cuda_bf16.h>
#include <cstdint>

#define B_    16
#define TRG_  512
#define SRC_  1024
#define ENC_  1024
#define TRGD_ 1024

// ---------------- packed bf16 hi/lo scratch (u32 = bf16x2 over k) -----------
__device__ uint32_t g_Hdh[(long)B_ * TRG_ * TRGD_ / 2];  // hidden   [t][d2]
__device__ uint32_t g_Hdl[(long)B_ * TRG_ * TRGD_ / 2];
__device__ uint32_t g_Eoh[(long)B_ * SRC_ * ENC_ / 2];   // enc_out  [s][e2]
__device__ uint32_t g_Eol[(long)B_ * SRC_ * ENC_ / 2];
__device__ uint32_t g_Wth[(long)ENC_ * TRGD_ / 2];       // W^T      [e][d2]
__device__ uint32_t g_Wtl[(long)ENC_ * TRGD_ / 2];
__device__ uint32_t g_Hph[(long)B_ * TRG_ * ENC_ / 2];   // hidden@W [t][e2]
__device__ uint32_t g_Hpl[(long)B_ * TRG_ * ENC_ / 2];
__device__ uint32_t g_Wgh[(long)B_ * TRG_ * SRC_ / 2];   // weights  [t][s2]
__device__ uint32_t g_Wgl[(long)B_ * TRG_ * SRC_ / 2];
__device__ uint32_t g_Evh[(long)B_ * SRC_ / 2 * TRGD_];  // enc_val  [s2][d] (NN pairs)
__device__ uint32_t g_Evl[(long)B_ * SRC_ / 2 * TRGD_];

// ---------------- helpers ----------------
__device__ __forceinline__ uint32_t s2u(const void* p) {
    uint32_t a;
    asm("{ .reg .u64 t; cvta.to.shared.u64 t, %1; cvt.u32.u64 %0, t; }"
        : "=r"(a) : "l"(p));
    return a;
}
__device__ __forceinline__ void bf16split2(float v0, float v1,
                                           uint32_t& ph, uint32_t& pl) {
    __nv_bfloat162 h = __floats2bfloat162_rn(v0, v1);
    ph = *reinterpret_cast<uint32_t*>(&h);
    float h0 = __uint_as_float(ph << 16);
    float h1 = __uint_as_float(ph & 0xFFFF0000u);
    __nv_bfloat162 l = __floats2bfloat162_rn(v0 - h0, v1 - h1);
    pl = *reinterpret_cast<uint32_t*>(&l);
}
__device__ __forceinline__ void cp16(uint32_t d, const void* s) {
    asm volatile("cp.async.cg.shared.global [%0], [%1], 16;" :: "r"(d), "l"(s));
}
#define CP_COMMIT() asm volatile("cp.async.commit_group;" ::: "memory")

#define MMA_BF16(acc, a0, a1, a2, a3, b0, b1) \
    asm volatile( \
        "mma.sync.aligned.m16n8k16.row.col.f32.bf16.bf16.f32 " \
        "{%0,%1,%2,%3}, {%4,%5,%6,%7}, {%8,%9}, {%0,%1,%2,%3};" \
        : "+f"((acc)[0]), "+f"((acc)[1]), "+f"((acc)[2]), "+f"((acc)[3]) \
        : "r"(a0), "r"(a1), "r"(a2), "r"(a3), "r"(b0), "r"(b1))

#define LDSM_X4(r, addr) \
    asm volatile("ldmatrix.sync.aligned.m8n8.x4.shared.b16 {%0,%1,%2,%3}, [%4];" \
        : "=r"((r)[0]), "=r"((r)[1]), "=r"((r)[2]), "=r"((r)[3]) : "r"(addr))

// ---------------------------------------------------------------------------
// bf16x3 GEMM: D[m,n] = sum_k A[m,k]*B[n,k]; inputs pre-split into separate
// hi/lo u32 arrays (bf16x2 over k). BM=BN=128, BK=32, 2-stage cp.async,
// 256 thr, warp tile 32x64, passes hh+hl+lh.
// Fragment loads via ldmatrix.x4 (A always; B when K-major).
//   BNN=false: B K-major packed [n][k2] -> smem [n][20] u32 (ldmatrix)
//   BNN=true : B NN pairs packed [k2][n] -> smem [k2][136] u32 (scalar LDS)
// EPI: 0 = fp32 out, 1 = masked fp32 out, 2 = packed bf16 h/l out.
// ---------------------------------------------------------------------------
template<int EPI, bool BNN>
__global__ __launch_bounds__(256, 2)
void gemm_bf16x3(const uint32_t* __restrict__ Ah, const uint32_t* __restrict__ Al,
                 const uint32_t* __restrict__ Bh, const uint32_t* __restrict__ Bl,
                 float* __restrict__ Cg, uint32_t* __restrict__ C2h,
                 uint32_t* __restrict__ C2l, const float* __restrict__ maskg,
                 int M, int N, int K, long sA, long sB, long sC)
{
    constexpr int STAGE = 10240;          // u32 per stage (40KB)
    constexpr int OAH = 0, OAL = 2560, OBH = 5120, OBL = 7680;

    extern __shared__ uint32_t smu[];

    const int tid  = threadIdx.x;
    const int wid  = tid >> 5, lane = tid & 31;
    const int wy   = wid >> 1, wx = wid & 1;
    const int bz   = blockIdx.z;
    const int bm   = blockIdx.y * 128, bn = blockIdx.x * 128;
    const int K2   = K >> 1;

    const uint32_t* Ah_ = Ah + (long)bz * sA + (long)bm * K2;
    const uint32_t* Al_ = Al + (long)bz * sA + (long)bm * K2;
    const uint32_t* Bh_ = BNN ? (Bh + (long)bz * sB)
                              : (Bh + (long)bz * sB + (long)bn * K2);
    const uint32_t* Bl_ = BNN ? (Bl + (long)bz * sB)
                              : (Bl + (long)bz * sB + (long)bn * K2);

    auto load_stage = [&](int s, int kc) {
        uint32_t* st = smu + s * STAGE;
        const int k2b = kc * 16;   // 16 u32 (=32 k) per chunk
#pragma unroll
        for (int i = 0; i < 2; i++) {
            int id = tid + 256 * i;
            int row = id >> 2, ch = (id & 3) * 4;
            cp16(s2u(st + OAH + row * 20 + ch), Ah_ + (long)row * K2 + k2b + ch);
            cp16(s2u(st + OAL + row * 20 + ch), Al_ + (long)row * K2 + k2b + ch);
        }
        if (BNN) {
#pragma unroll
            for (int i = 0; i < 2; i++) {
                int id = tid + 256 * i;
                int r = id >> 5, c = (id & 31) * 4;
                cp16(s2u(st + OBH + r * 136 + c), Bh_ + (long)(k2b + r) * N + bn + c);
                cp16(s2u(st + OBL + r * 136 + c), Bl_ + (long)(k2b + r) * N + bn + c);
            }
        } else {
#pragma unroll
            for (int i = 0; i < 2; i++) {
                int id = tid + 256 * i;
                int row = id >> 2, ch = (id & 3) * 4;
                cp16(s2u(st + OBH + row * 20 + ch), Bh_ + (long)row * K2 + k2b + ch);
                cp16(s2u(st + OBL + row * 20 + ch), Bl_ + (long)row * K2 + k2b + ch);
            }
        }
    };

    float acc[2][8][4];
#pragma unroll
    for (int i = 0; i < 2; i++)
#pragma unroll
        for (int j = 0; j < 8; j++)
#pragma unroll
            for (int v = 0; v < 4; v++) acc[i][j][v] = 0.0f;

    const int nch = K / 32;
    load_stage(0, 0); CP_COMMIT();

    // ldmatrix lane addressing (byte offsets relative to smu base)
    const int lr = lane & 7, lg = lane >> 3;
    const uint32_t smuB = s2u(smu);
    // A: matrix g -> rows m0 + (g&1)*8, k2-off (g>>1)*4
    const uint32_t aOff = ((wy * 32 + lr + (lg & 1) * 8) * 20 + (lg >> 1) * 4) * 4;
    const uint32_t aHb = smuB + OAH * 4 + aOff;
    const uint32_t aLb = smuB + OAL * 4 + aOff;
    // B (K-major): matrix g -> rows n0 + (g>>1)*8 (j/j+1), k2-off (g&1)*4
    const uint32_t bOff = ((wx * 64 + (lg >> 1) * 8 + lr) * 20 + (lg & 1) * 4) * 4;
    const uint32_t bHb = smuB + OBH * 4 + bOff;
    const uint32_t bLb = smuB + OBL * 4 + bOff;
    // BNN scalar B base (u32 index within stage arrays)
    const int bBaseNN = (lane & 3) * 136 + wx * 64 + (lane >> 2);

    for (int kc = 0; kc < nch; kc++) {
        if (kc + 1 < nch) {
            load_stage((kc + 1) & 1, kc + 1);
            CP_COMMIT();
            asm volatile("cp.async.wait_group 1;" ::: "memory");
        } else {
            asm volatile("cp.async.wait_group 0;" ::: "memory");
        }
        __syncthreads();

        const uint32_t stg = (kc & 1) * (STAGE * 4);   // stage byte offset
        const uint32_t* st  = smu + (kc & 1) * STAGE;
        const uint32_t* sBh = st + OBH;
        const uint32_t* sBl = st + OBL;

#pragma unroll
        for (int ks = 0; ks < 2; ks++) {
            uint32_t ah[2][4], al[2][4];
#pragma unroll
            for (int i = 0; i < 2; i++) {
                LDSM_X4(ah[i], aHb + stg + i * 1280 + ks * 32);
                LDSM_X4(al[i], aLb + stg + i * 1280 + ks * 32);
            }

            if (!BNN) {
#pragma unroll
                for (int jj = 0; jj < 8; jj += 2) {
                    uint32_t bh[4], bl[4];
                    LDSM_X4(bh, bHb + stg + jj * 640 + ks * 32);
                    LDSM_X4(bl, bLb + stg + jj * 640 + ks * 32);
#pragma unroll
                    for (int j2 = 0; j2 < 2; j2++) {
                        const int j = jj + j2;
                        const uint32_t b0h = bh[j2 * 2], b1h = bh[j2 * 2 + 1];
                        const uint32_t b0l = bl[j2 * 2], b1l = bl[j2 * 2 + 1];
                        MMA_BF16(acc[0][j], ah[0][0], ah[0][1], ah[0][2], ah[0][3], b0h, b1h);
                        MMA_BF16(acc[1][j], ah[1][0], ah[1][1], ah[1][2], ah[1][3], b0h, b1h);
                        MMA_BF16(acc[0][j], ah[0][0], ah[0][1], ah[0][2], ah[0][3], b0l, b1l);
                        MMA_BF16(acc[1][j], ah[1][0], ah[1][1], ah[1][2], ah[1][3], b0l, b1l);
                        MMA_BF16(acc[0][j], al[0][0], al[0][1], al[0][2], al[0][3], b0h, b1h);
                        MMA_BF16(acc[1][j], al[1][0], al[1][1], al[1][2], al[1][3], b0h, b1h);
                    }
                }
            } else {
                const int bk = bBaseNN + ks * 8 * 136;
                auto loadB = [&](int j, uint32_t* bh, uint32_t* bl) {
                    const int o = bk + j * 8;
                    bh[0] = sBh[o]; bh[1] = sBh[o + 544];   // +4*136
                    bl[0] = sBl[o]; bl[1] = sBl[o + 544];
                };
                uint32_t bh0[2], bl0[2], bh1[2], bl1[2];
                loadB(0, bh0, bl0);
#pragma unroll
                for (int j = 0; j < 8; j++) {
                    uint32_t* bh = (j & 1) ? bh1 : bh0;
                    uint32_t* bl = (j & 1) ? bl1 : bl0;
                    if (j < 7) loadB(j + 1, (j & 1) ? bh0 : bh1, (j & 1) ? bl0 : bl1);
                    MMA_BF16(acc[0][j], ah[0][0], ah[0][1], ah[0][2], ah[0][3], bh[0], bh[1]);
                    MMA_BF16(acc[1][j], ah[1][0], ah[1][1], ah[1][2], ah[1][3], bh[0], bh[1]);
                    MMA_BF16(acc[0][j], ah[0][0], ah[0][1], ah[0][2], ah[0][3], bl[0], bl[1]);
                    MMA_BF16(acc[1][j], ah[1][0], ah[1][1], ah[1][2], ah[1][3], bl[0], bl[1]);
                    MMA_BF16(acc[0][j], al[0][0], al[0][1], al[0][2], al[0][3], bh[0], bh[1]);
                    MMA_BF16(acc[1][j], al[1][0], al[1][1], al[1][2], al[1][3], bh[0], bh[1]);
                }
            }
        }
        __syncthreads();
    }

    // epilogue
    const int N2 = N >> 1;
#pragma unroll
    for (int i = 0; i < 2; i++) {
        const int row = bm + wy * 32 + i * 16 + (lane >> 2);
#pragma unroll
        for (int j = 0; j < 8; j++) {
            const int col = bn + wx * 64 + j * 8 + (lane & 3) * 2;
            float v0 = acc[i][j][0], v1 = acc[i][j][1];
            float v2 = acc[i][j][2], v3 = acc[i][j][3];
            if (EPI == 2) {
                uint32_t ph, pl;
                bf16split2(v0, v1, ph, pl);
                C2h[(long)row * N2 + (col >> 1)] = ph;
                C2l[(long)row * N2 + (col >> 1)] = pl;
                bf16split2(v2, v3, ph, pl);
                C2h[(long)(row + 8) * N2 + (col >> 1)] = ph;
                C2l[(long)(row + 8) * N2 + (col >> 1)] = pl;
            } else {
                float* C = Cg + (long)bz * sC;
                if (EPI == 1) {
                    float m0 = maskg[(long)bz * N + col];
                    float m1 = maskg[(long)bz * N + col + 1];
                    v0 *= m0; v1 *= m1; v2 *= m0; v3 *= m1;
                }
                float2 p01; p01.x = v0; p01.y = v1;
                float2 p23; p23.x = v2; p23.y = v3;
                *reinterpret_cast<float2*>(&C[(long)row * N + col]) = p01;
                *reinterpret_cast<float2*>(&C[(long)(row + 8) * N + col]) = p23;
            }
        }
    }
}

// ---------------- split kernels (vectorized: 4 outputs/thread) --------------
__global__ __launch_bounds__(256)
void split_pack_k(const float4* __restrict__ in, uint4* __restrict__ h,
                  uint4* __restrict__ l, long nv)
{
    long i = (long)blockIdx.x * blockDim.x + threadIdx.x;
    if (i < nv) {
        float4 a = in[2 * i];
        float4 b = in[2 * i + 1];
        uint4 ho, lo;
        bf16split2(a.x, a.y, ho.x, lo.x);
        bf16split2(a.z, a.w, ho.y, lo.y);
        bf16split2(b.x, b.y, ho.z, lo.z);
        bf16split2(b.z, b.w, ho.w, lo.w);
        h[i] = ho; l[i] = lo;
    }
}

// W[d][e] -> packed transpose Wt[e][d2] (pairs over d)
__global__ __launch_bounds__(256)
void transpose_split_pack_k(const float* __restrict__ W,
                            uint32_t* __restrict__ th, uint32_t* __restrict__ tl)
{
    __shared__ float t[32][33];
    const int d0 = blockIdx.y * 32, e0 = blockIdx.x * 32;
    const int x = threadIdx.x & 31, y = threadIdx.x >> 5;
#pragma unroll
    for (int i = 0; i < 4; i++)
        t[y + 8 * i][x] = W[(long)(d0 + y + 8 * i) * ENC_ + e0 + x];
    __syncthreads();
#pragma unroll
    for (int it = 0; it < 2; it++) {
        int idx = threadIdx.x + 256 * it;
        int e = idx >> 4, d2 = idx & 15;
        uint32_t ph, pl;
        bf16split2(t[2 * d2][e], t[2 * d2 + 1][e], ph, pl);
        th[(long)(e0 + e) * (TRGD_ / 2) + (d0 >> 1) + d2] = ph;
        tl[(long)(e0 + e) * (TRGD_ / 2) + (d0 >> 1) + d2] = pl;
    }
}

// enc_val row pairs: Ev[s][d] -> packed [s2][d]; 4 columns per thread
__global__ __launch_bounds__(256)
void pack_rows2_k(const float* __restrict__ in, uint4* __restrict__ h,
                  uint4* __restrict__ l)
{
    const int r = blockIdx.x;                            // global s2 row
    const int c = threadIdx.x * 4;                       // d (TRGD_/4 = 256 thr)
    float4 a = *reinterpret_cast<const float4*>(in + (long)(2 * r) * TRGD_ + c);
    float4 b = *reinterpret_cast<const float4*>(in + (long)(2 * r + 1) * TRGD_ + c);
    uint4 ho, lo;
    bf16split2(a.x, b.x, ho.x, lo.x);
    bf16split2(a.y, b.y, ho.y, lo.y);
    bf16split2(a.z, b.z, ho.z, lo.z);
    bf16split2(a.w, b.w, ho.w, lo.w);
    const long p = ((long)r * TRGD_ + c) >> 2;
    h[p] = ho; l[p] = lo;
}

// ---------------- masked softmax; exact fp32 + packed h/l outputs ----------
__global__ __launch_bounds__(256)
void masked_softmax_k(const float* __restrict__ energ, const float* __restrict__ mask,
                      float* __restrict__ wout, uint32_t* __restrict__ wh,
                      uint32_t* __restrict__ wl)
{
    const int row = blockIdx.x;
    const int b = row >> 9;
    const float4* xr = reinterpret_cast<const float4*>(energ + (long)row * SRC_);
    const float4* mr = reinterpret_cast<const float4*>(mask + (long)b * SRC_);
    float4* wr = reinterpret_cast<float4*>(wout + (long)row * SRC_);
    const int t = threadIdx.x;

    float4 xv = xr[t];
    float4 mv = mr[t];
    xv.x *= mv.x; xv.y *= mv.y; xv.z *= mv.z; xv.w *= mv.w;

    float lmax = fmaxf(fmaxf(xv.x, xv.y), fmaxf(xv.z, xv.w));
#pragma unroll
    for (int o = 16; o; o >>= 1)
        lmax = fmaxf(lmax, __shfl_xor_sync(0xffffffffu, lmax, o));

    __shared__ float redm[8];
    __shared__ float reds[8];
    if ((t & 31) == 0) redm[t >> 5] = lmax;
    __syncthreads();
    float bmax = fmaxf(fmaxf(fmaxf(redm[0], redm[1]), fmaxf(redm[2], redm[3])),
                       fmaxf(fmaxf(redm[4], redm[5]), fmaxf(redm[6], redm[7])));

    float4 ev;
    ev.x = expf(xv.x - bmax) * mv.x;
    ev.y = expf(xv.y - bmax) * mv.y;
    ev.z = expf(xv.z - bmax) * mv.z;
    ev.w = expf(xv.w - bmax) * mv.w;

    float lsum = ev.x + ev.y + ev.z + ev.w;
#pragma unroll
    for (int o = 16; o; o >>= 1)
        lsum += __shfl_xor_sync(0xffffffffu, lsum, o);
    if ((t & 31) == 0) reds[t >> 5] = lsum;
    __syncthreads();
    float bsum = reds[0] + reds[1] + reds[2] + reds[3] +
                 reds[4] + reds[5] + reds[6] + reds[7];

    float inv = 1.0f / (bsum + 1e-6f);
    ev.x *= inv; ev.y *= inv; ev.z *= inv; ev.w *= inv;
    wr[t] = ev;

    uint32_t ph, pl;
    const long p = (long)row * (SRC_ / 2) + 2 * t;
    bf16split2(ev.x, ev.y, ph, pl);
    wh[p] = ph; wl[p] = pl;
    bf16split2(ev.z, ev.w, ph, pl);
    wh[p + 1] = ph; wl[p + 1] = pl;
}

// ---------------- launch ----------------
extern "C" void kernel_launch(void* const* d_in, const int* in_sizes, int n_in,
                              void* d_out, int out_size)
{
    const float* hidden  = (const float*)d_in[0];   // (B, TRG, TRGD)
    const float* enc_out = (const float*)d_in[1];   // (B, SRC, ENC)
    const float* enc_val = (const float*)d_in[2];   // (B, SRC, TRGD)
    const float* mask    = (const float*)d_in[3];   // (B, SRC)
    const float* W       = (const float*)d_in[4];   // (TRGD, ENC)

    float* out      = (float*)d_out;
    float* context  = out;                           // (B, TRG, TRGD)
    float* weights  = out + (long)B_ * TRG_ * SRC_;  // (B, TRG, SRC)
    float* energies = out + 2L * B_ * TRG_ * SRC_;   // (B, TRG, SRC)

    uint32_t *Hdh, *Hdl, *Eoh, *Eol, *Wth, *Wtl, *Hph, *Hpl, *Wgh, *Wgl, *Evh, *Evl;
    cudaGetSymbolAddress((void**)&Hdh, g_Hdh);
    cudaGetSymbolAddress((void**)&Hdl, g_Hdl);
    cudaGetSymbolAddress((void**)&Eoh, g_Eoh);
    cudaGetSymbolAddress((void**)&Eol, g_Eol);
    cudaGetSymbolAddress((void**)&Wth, g_Wth);
    cudaGetSymbolAddress((void**)&Wtl, g_Wtl);
    cudaGetSymbolAddress((void**)&Hph, g_Hph);
    cudaGetSymbolAddress((void**)&Hpl, g_Hpl);
    cudaGetSymbolAddress((void**)&Wgh, g_Wgh);
    cudaGetSymbolAddress((void**)&Wgl, g_Wgl);
    cudaGetSymbolAddress((void**)&Evh, g_Evh);
    cudaGetSymbolAddress((void**)&Evl, g_Evl);

    const size_t dyn = 2UL * 10240 * 4;   // 81,920 B
    cudaFuncSetAttribute(gemm_bf16x3<2, false>,
                         cudaFuncAttributeMaxDynamicSharedMemorySize, dyn);
    cudaFuncSetAttribute(gemm_bf16x3<1, false>,
                         cudaFuncAttributeMaxDynamicSharedMemorySize, dyn);
    cudaFuncSetAttribute(gemm_bf16x3<0, true>,
                         cudaFuncAttributeMaxDynamicSharedMemorySize, dyn);

    // splits (vectorized)
    {
        long nv = (long)B_ * TRG_ * TRGD_ / 8;   // 4 pairs per thread
        split_pack_k<<<(unsigned)((nv + 255) / 256), 256>>>(
            (const float4*)hidden, (uint4*)Hdh, (uint4*)Hdl, nv);
    }
    {
        long nv = (long)B_ * SRC_ * ENC_ / 8;
        split_pack_k<<<(unsigned)((nv + 255) / 256), 256>>>(
            (const float4*)enc_out, (uint4*)Eoh, (uint4*)Eol, nv);
    }
    transpose_split_pack_k<<<dim3(ENC_ / 32, TRGD_ / 32), 256>>>(W, Wth, Wtl);
    pack_rows2_k<<<B_ * SRC_ / 2, TRGD_ / 4>>>(enc_val, (uint4*)Evh, (uint4*)Evl);

    // 1) Hp = hidden @ W  -> packed bf16 h/l   (A=hidden, B=Wt, K-major)
    {
        dim3 grid(ENC_ / 128, (B_ * TRG_) / 128, 1);
        gemm_bf16x3<2, false><<<grid, 256, dyn>>>(
            Hdh, Hdl, Wth, Wtl, nullptr, Hph, Hpl, nullptr,
            B_ * TRG_, ENC_, TRGD_, 0, 0, 0);
    }
    // 2) energies[b] = (Hp[b] @ enc_out[b]^T) * mask[b]
    {
        dim3 grid(SRC_ / 128, TRG_ / 128, B_);
        gemm_bf16x3<1, false><<<grid, 256, dyn>>>(
            Hph, Hpl, Eoh, Eol, energies, nullptr, nullptr, mask,
            TRG_, SRC_, ENC_,
            (long)TRG_ * ENC_ / 2, (long)SRC_ * ENC_ / 2, (long)TRG_ * SRC_);
    }
    // 3) masked softmax -> weights (fp32) + packed h/l
    masked_softmax_k<<<B_ * TRG_, 256>>>(energies, mask, weights, Wgh, Wgl);

    // 4) context[b] = weights[b] @ enc_val[b]   (B NN pairs layout)
    {
        dim3 grid(TRGD_ / 128, TRG_ / 128, B_);
        gemm_bf16x3<0, true><<<grid, 256, dyn>>>(
            Wgh, Wgl, Evh, Evl, context, nullptr, nullptr, nullptr,
            TRG_, TRGD_, SRC_,
            (long)TRG_ * SRC_ / 2, (long)SRC_ / 2 * TRGD_, (long)TRG_ * TRGD_);
    }
}